// round 15
// baseline (speedup 1.0000x reference)
#include <cuda_runtime.h>
#include <cuda.h>
#include <cuda_fp16.h>
#include <math.h>
#include <stdint.h>

// Problem constants
#define BB 2
#define SS 2048
#define DD 1024
#define HH 16
#define HD 64
#define WW 16
#define DFF 4096
#define MM (BB * SS)   // 4096 rows

// ---------------- scratch (no allocations allowed) ----------------
__device__ __half g_qkv_h[MM * 3 * DD];       // QKV fp16
__device__ float g_x1[MM * DD];               // residual-1 output fp32
__device__ __half g_h_h[MM * DD];             // LN1 out fp16
__device__ __half g_at_h[MM * DD];            // attn out fp16
__device__ __half g_xn_h[MM * DD];            // LN2 out fp16
__device__ __half g_ff_h[MM * DFF];           // MLP hidden fp16
__device__ __half g_wq_h[3 * DD * DD];
__device__ __half g_wo_h[DD * DD];
__device__ __half g_w1_h[DFF * DD];
__device__ __half g_w2_h[DD * DFF];

__device__ __forceinline__ uint32_t smem_u32(const void* p) {
    return (uint32_t)__cvta_generic_to_shared(p);
}

__device__ __forceinline__ float gelu_tanh(float x) {
    float x3 = x * x * x;
    return 0.5f * x * (1.0f + tanhf(0.7978845608028654f * (x + 0.044715f * x3)));
}

__device__ __forceinline__ void cvt_block(const float* __restrict__ in,
                                          __half* __restrict__ out, int base) {
    int i = base * 1024 + threadIdx.x * 4;
    float4 v = *(const float4*)(in + i);
    *(__half2*)(out + i)     = __floats2half2_rn(v.x, v.y);
    *(__half2*)(out + i + 2) = __floats2half2_rn(v.z, v.w);
}

// ---------------- LN1 + wq convert, co-scheduled ----------------
// blocks [0, MM): LayerNorm rows; blocks [MM, MM+3072): wq fp32->fp16
__global__ void ln_cvt_kernel(const float* __restrict__ x,
                              const float* __restrict__ g,
                              const float* __restrict__ b,
                              __half* __restrict__ y,
                              const float* __restrict__ wq,
                              __half* __restrict__ owq) {
    if (blockIdx.x >= MM) {
        cvt_block(wq, owq, blockIdx.x - MM);
        return;
    }
    int row = blockIdx.x;
    const float* xp = x + (size_t)row * DD;
    int i = threadIdx.x * 4;
    float4 xv = *(const float4*)(xp + i);
    float s  = xv.x + xv.y + xv.z + xv.w;
    float ss = xv.x*xv.x + xv.y*xv.y + xv.z*xv.z + xv.w*xv.w;
    for (int o = 16; o > 0; o >>= 1) {
        s  += __shfl_xor_sync(0xffffffffu, s,  o);
        ss += __shfl_xor_sync(0xffffffffu, ss, o);
    }
    __shared__ float sh_s[8], sh_ss[8];
    int wid = threadIdx.x >> 5, lane = threadIdx.x & 31;
    if (lane == 0) { sh_s[wid] = s; sh_ss[wid] = ss; }
    __syncthreads();
    if (wid == 0) {
        s  = (lane < 8) ? sh_s[lane]  : 0.f;
        ss = (lane < 8) ? sh_ss[lane] : 0.f;
        for (int o = 4; o > 0; o >>= 1) {
            s  += __shfl_xor_sync(0xffffffffu, s,  o);
            ss += __shfl_xor_sync(0xffffffffu, ss, o);
        }
        if (lane == 0) { sh_s[0] = s; sh_ss[0] = ss; }
    }
    __syncthreads();
    float mean = sh_s[0] * (1.0f / DD);
    float var  = sh_ss[0] * (1.0f / DD) - mean * mean;
    float inv  = rsqrtf(var + 1e-5f);
    float4 gv = *(const float4*)(g + i);
    float4 bv = *(const float4*)(b + i);
    float o0 = (xv.x - mean) * inv * gv.x + bv.x;
    float o1 = (xv.y - mean) * inv * gv.y + bv.y;
    float o2 = (xv.z - mean) * inv * gv.z + bv.z;
    float o3 = (xv.w - mean) * inv * gv.w + bv.w;
    size_t idx = (size_t)row * DD + i;
    *(__half2*)(y + idx)     = __floats2half2_rn(o0, o1);
    *(__half2*)(y + idx + 2) = __floats2half2_rn(o2, o3);
}

// ---------------- LayerNorm -> fp16 (standalone, for LN2) ----------------
__global__ void ln_half_kernel(const float* __restrict__ x,
                               const float* __restrict__ g,
                               const float* __restrict__ b,
                               __half* __restrict__ y) {
    int row = blockIdx.x;
    const float* xp = x + (size_t)row * DD;
    int i = threadIdx.x * 4;
    float4 xv = *(const float4*)(xp + i);
    float s  = xv.x + xv.y + xv.z + xv.w;
    float ss = xv.x*xv.x + xv.y*xv.y + xv.z*xv.z + xv.w*xv.w;
    for (int o = 16; o > 0; o >>= 1) {
        s  += __shfl_xor_sync(0xffffffffu, s,  o);
        ss += __shfl_xor_sync(0xffffffffu, ss, o);
    }
    __shared__ float sh_s[8], sh_ss[8];
    int wid = threadIdx.x >> 5, lane = threadIdx.x & 31;
    if (lane == 0) { sh_s[wid] = s; sh_ss[wid] = ss; }
    __syncthreads();
    if (wid == 0) {
        s  = (lane < 8) ? sh_s[lane]  : 0.f;
        ss = (lane < 8) ? sh_ss[lane] : 0.f;
        for (int o = 4; o > 0; o >>= 1) {
            s  += __shfl_xor_sync(0xffffffffu, s,  o);
            ss += __shfl_xor_sync(0xffffffffu, ss, o);
        }
        if (lane == 0) { sh_s[0] = s; sh_ss[0] = ss; }
    }
    __syncthreads();
    float mean = sh_s[0] * (1.0f / DD);
    float var  = sh_ss[0] * (1.0f / DD) - mean * mean;
    float inv  = rsqrtf(var + 1e-5f);
    float4 gv = *(const float4*)(g + i);
    float4 bv = *(const float4*)(b + i);
    float o0 = (xv.x - mean) * inv * gv.x + bv.x;
    float o1 = (xv.y - mean) * inv * gv.y + bv.y;
    float o2 = (xv.z - mean) * inv * gv.z + bv.z;
    float o3 = (xv.w - mean) * inv * gv.w + bv.w;
    size_t idx = (size_t)row * DD + i;
    *(__half2*)(y + idx)     = __floats2half2_rn(o0, o1);
    *(__half2*)(y + idx + 2) = __floats2half2_rn(o2, o3);
}

// ---------------- TMA + mma.sync fp16 GEMM: C[M,N] = A[M,K] @ Bw[N,K]^T (+epi) ----------------
// 3-stage TMA pipeline, full/empty mbarriers, fence.proxy.async for cross-proxy safety.
// Tile bases MUST be 1024B-aligned so the manual swizzle matches TMA's.
// epi: 0 = +bias -> fp16 ; 1 = fp32 +bias+res ; 2 = gelu(+bias) -> fp16
#define BKT 64
#define TILE_BYTES (128 * 128)          // 16384 (64 fp16 = 128 B per row)
#define OFF_A 0
#define OFF_B TILE_BYTES
#define STAGE_BYTES (2 * TILE_BYTES)    // 32768
#define NSTAGE 3
#define GEMM_SMEM (NSTAGE * STAGE_BYTES + 1024)  // 99328 (1KB alignment slack)

#define LDMX4(r0, r1, r2, r3, addr) \
    asm volatile("ldmatrix.sync.aligned.m8n8.x4.shared.b16 {%0,%1,%2,%3}, [%4];" \
                 : "=r"(r0), "=r"(r1), "=r"(r2), "=r"(r3) : "r"(addr))

#define MMA_F16(d, a, b0, b1) \
    asm volatile("mma.sync.aligned.m16n8k16.row.col.f32.f16.f16.f32 " \
                 "{%0,%1,%2,%3}, {%4,%5,%6,%7}, {%8,%9}, {%0,%1,%2,%3};" \
                 : "+f"((d)[0]), "+f"((d)[1]), "+f"((d)[2]), "+f"((d)[3]) \
                 : "r"((a)[0]), "r"((a)[1]), "r"((a)[2]), "r"((a)[3]), "r"(b0), "r"(b1))

#define MBAR_INIT(mbar, cnt) \
    asm volatile("mbarrier.init.shared.b64 [%0], %1;" :: "r"(mbar), "r"(cnt) : "memory")

#define MBAR_EXPECT(mbar, bytes) \
    asm volatile("mbarrier.arrive.expect_tx.shared.b64 _, [%0], %1;" :: "r"(mbar), "r"(bytes) : "memory")

#define MBAR_ARRIVE(mbar) \
    asm volatile("mbarrier.arrive.release.cta.shared::cta.b64 _, [%0];" :: "r"(mbar) : "memory")

#define FENCE_ASYNC() \
    asm volatile("fence.proxy.async.shared::cta;" ::: "memory")

#define MBAR_WAIT(mbar, parity) do {                                            \
    uint32_t _m = (mbar); uint32_t _p = (parity); uint32_t _d;                  \
    asm volatile("{\n\t.reg .pred p;\n\t"                                       \
        "mbarrier.try_wait.parity.acquire.cta.shared::cta.b64 p, [%1], %2;\n\t" \
        "selp.b32 %0, 1, 0, p;\n\t}"                                            \
        : "=r"(_d) : "r"(_m), "r"(_p) : "memory");                              \
    if (!_d) {                                                                  \
        asm volatile("{\n\t.reg .pred P1;\n\t"                                  \
            "WL_%=:\n\t"                                                        \
            "mbarrier.try_wait.parity.acquire.cta.shared::cta.b64 P1, [%0], %1, 0x989680;\n\t" \
            "@P1 bra.uni WD_%=;\n\t"                                            \
            "bra.uni WL_%=;\n\t"                                                \
            "WD_%=:\n\t}" :: "r"(_m), "r"(_p) : "memory");                      \
    }                                                                           \
} while (0)

#define TMA_LD2D(smem, tmap, cx, cy, mbar) \
    asm volatile("cp.async.bulk.tensor.2d.shared::cta.global.tile.mbarrier::complete_tx::bytes " \
                 "[%0], [%1, {%2, %3}], [%4];" \
                 :: "r"(smem), "l"(tmap), "r"(cx), "r"(cy), "r"(mbar) : "memory")

// swizzled byte offset inside one 128x64(fp16) tile: row r (0..127), 16B unit u (0..7)
// valid ONLY when tile base is 1024B-aligned
__device__ __forceinline__ uint32_t sw_off(int r, int u) {
    return (uint32_t)(r * 128 + ((u ^ (r & 7)) << 4));
}

__global__ __launch_bounds__(256, 2)
void gemmh(const __grid_constant__ CUtensorMap tmA,
           const __grid_constant__ CUtensorMap tmB,
           const float* __restrict__ bias, const float* __restrict__ res,
           float* __restrict__ outF, __half* __restrict__ outH,
           int Nn, int Kk, int epi) {
    extern __shared__ __align__(128) char dsm[];
    __shared__ __align__(8) uint64_t s_full[NSTAGE];
    __shared__ __align__(8) uint64_t s_empty[NSTAGE];
    uint32_t sbase = (smem_u32(dsm) + 1023) & ~1023u;   // 1024B-align: swizzle phase contract
    int tid = threadIdx.x;
    int lane = tid & 31;
    int wid = tid >> 5;
    int wr = wid & 1;      // warp row: m offset wr*64
    int wc = wid >> 1;     // warp col: n offset wc*32
    int bm = blockIdx.y * 128;
    int bn = blockIdx.x * 128;

    float acc[4][4][4];
    #pragma unroll
    for (int mi = 0; mi < 4; mi++)
        #pragma unroll
        for (int ni = 0; ni < 4; ni++)
            #pragma unroll
            for (int q = 0; q < 4; q++) acc[mi][ni][q] = 0.f;

    const int NC = Kk >> 6;   // BKT=64 chunks

    if (tid == 0) {
        #pragma unroll
        for (int s = 0; s < NSTAGE; s++) {
            MBAR_INIT(smem_u32(&s_full[s]), 1);
            MBAR_INIT(smem_u32(&s_empty[s]), 256);
        }
    }
    __syncthreads();

    // prologue: issue chunks 0, 1
    if (tid == 0) {
        FENCE_ASYNC();   // order barrier inits (generic) before async-proxy use
        #pragma unroll
        for (int c0 = 0; c0 < 2; c0++) {
            if (c0 < NC) {
                uint32_t st = sbase + c0 * STAGE_BYTES;
                uint32_t mb = smem_u32(&s_full[c0]);
                MBAR_EXPECT(mb, STAGE_BYTES);
                TMA_LD2D(st + OFF_A, &tmA, c0 << 6, bm, mb);
                TMA_LD2D(st + OFF_B, &tmB, c0 << 6, bn, mb);
            }
        }
    }

    int a_row = wr * 64 + (lane & 15);
    int a_usel = (lane >> 4) & 1;
    int b_row = wc * 32 + (lane & 7) + ((lane >> 4) & 1) * 8;
    int b_usel = (lane >> 3) & 1;

    for (int c = 0; c < NC; c++) {
        int stg = c % NSTAGE;
        MBAR_WAIT(smem_u32(&s_full[stg]), (c / NSTAGE) & 1);

        uint32_t st = sbase + stg * STAGE_BYTES;
        #pragma unroll
        for (int kk = 0; kk < 4; kk++) {
            uint32_t bh[8];
            #pragma unroll
            for (int g = 0; g < 2; g++) {
                int r = b_row + g * 16;
                uint32_t off = sw_off(r, kk * 2 + b_usel);
                LDMX4(bh[g*4+0], bh[g*4+1], bh[g*4+2], bh[g*4+3], st + OFF_B + off);
            }
            #pragma unroll
            for (int mi = 0; mi < 4; mi++) {
                uint32_t ah[4];
                int r = a_row + mi * 16;
                uint32_t off = sw_off(r, kk * 2 + a_usel);
                LDMX4(ah[0], ah[1], ah[2], ah[3], st + OFF_A + off);
                #pragma unroll
                for (int ni = 0; ni < 4; ni++) {
                    MMA_F16(acc[mi][ni], ah, bh[ni*2], bh[ni*2+1]);
                }
            }
        }
        // consumer done with this stage's smem (release pairs with producer acquire)
        MBAR_ARRIVE(smem_u32(&s_empty[stg]));

        if (tid == 0 && c + 2 < NC) {
            int cn = c + 2;
            int sn = cn % NSTAGE;
            if (cn >= NSTAGE)
                MBAR_WAIT(smem_u32(&s_empty[sn]), (cn / NSTAGE - 1) & 1);
            // order all consumers' generic-proxy reads before the async-proxy TMA write
            FENCE_ASYNC();
            uint32_t st2 = sbase + sn * STAGE_BYTES;
            uint32_t mb = smem_u32(&s_full[sn]);
            MBAR_EXPECT(mb, STAGE_BYTES);
            TMA_LD2D(st2 + OFF_A, &tmA, cn << 6, bm, mb);
            TMA_LD2D(st2 + OFF_B, &tmB, cn << 6, bn, mb);
        }
    }

    // epilogue
    int m0 = bm + wr * 64 + (lane >> 2);
    int n0 = bn + wc * 32 + (lane & 3) * 2;
    #pragma unroll
    for (int mi = 0; mi < 4; mi++) {
        #pragma unroll
        for (int r2 = 0; r2 < 2; r2++) {
            int row = m0 + mi * 16 + r2 * 8;
            size_t rbase = (size_t)row * Nn;
            #pragma unroll
            for (int ni = 0; ni < 4; ni++) {
                int col = n0 + ni * 8;
                float v0 = acc[mi][ni][r2*2+0] + bias[col];
                float v1 = acc[mi][ni][r2*2+1] + bias[col+1];
                if (epi == 0) {
                    *(__half2*)(outH + rbase + col) = __floats2half2_rn(v0, v1);
                } else if (epi == 1) {
                    float2 rv = *(const float2*)(res + rbase + col);
                    *(float2*)(outF + rbase + col) = make_float2(v0 + rv.x, v1 + rv.y);
                } else {
                    v0 = gelu_tanh(v0); v1 = gelu_tanh(v1);
                    *(__half2*)(outH + rbase + col) = __floats2half2_rn(v0, v1);
                }
            }
        }
    }
}

// ---------------- attention + wo/w1/w2 convert, co-scheduled ----------------
// blocks [0, 1024): sliding-window attention (dual-query warps, Q/K/V smem)
// blocks [1024, 1024+9216): weight converts (soak idle DRAM bw under attn)
#define TQ 64
#define KR (TQ + WW - 1)     // 79 key rows
#define PKH 72               // halves per smem row (144B, 16B-aligned rows)
#define ATTN_BLOCKS 1024
#define CVT_BLOCKS (1024 + 4096 + 4096)
#define ATTN_SMEM ((2 * 80 + 64) * PKH * 2)   // K + V + Q = 32256 bytes

__global__ __launch_bounds__(256, 6)
void attn_cvt_kernel(const __half* __restrict__ qkv,
                     __half* __restrict__ oh,
                     const float* __restrict__ wo, __half* __restrict__ owo,
                     const float* __restrict__ w1, __half* __restrict__ ow1,
                     const float* __restrict__ w2, __half* __restrict__ ow2) {
    int blk = blockIdx.x;
    if (blk >= ATTN_BLOCKS) {
        int i = blk - ATTN_BLOCKS;
        if (i < 1024)       cvt_block(wo, owo, i);
        else if (i < 5120)  cvt_block(w1, ow1, i - 1024);
        else                cvt_block(w2, ow2, i - 5120);
        return;
    }

    extern __shared__ __align__(16) __half asm_h[];
    __half* Ks = asm_h;                 // [80][PKH]
    __half* Vs = asm_h + 80 * PKH;      // [80][PKH]
    __half* Qs = asm_h + 160 * PKH;     // [64][PKH]

    int tile = blk & 31;
    int h = (blk >> 5) & 15;
    int b = blk >> 9;
    int s0 = tile * TQ;
    int tid = threadIdx.x;
    int lane = tid & 31;
    int w = tid >> 5;

    // cooperative K/V load: 79 rows x 64 halves, 16B chunks; zero-fill seq<0 rows
    for (int i = tid; i < KR * (HD / 8); i += 256) {
        int r = i >> 3;
        int c = (i & 7) * 8;
        int seq = s0 - (WW - 1) + r;
        if (seq >= 0) {
            size_t base = ((size_t)(b * SS + seq)) * (3 * DD) + h * HD + c;
            *(float4*)&Ks[r * PKH + c] = *(const float4*)(qkv + base + DD);
            *(float4*)&Vs[r * PKH + c] = *(const float4*)(qkv + base + 2 * DD);
        } else {
            float4 z = make_float4(0.f, 0.f, 0.f, 0.f);
            *(float4*)&Ks[r * PKH + c] = z;
            *(float4*)&Vs[r * PKH + c] = z;
        }
    }
    // cooperative Q load: 64 rows x 64 halves
    for (int i = tid; i < TQ * (HD / 8); i += 256) {
        int r = i >> 3;
        int c = (i & 7) * 8;
        size_t base = ((size_t)(b * SS + s0 + r)) * (3 * DD) + h * HD + c;
        *(float4*)&Qs[r * PKH + c] = *(const float4*)(qkv + base);
    }
    __syncthreads();

    int half = lane >> 4;   // 0: query A, 1: query B
    int hl = lane & 15;     // key offset j for the score phase

    for (int qq = 0; qq < 4; qq++) {
        int qi = w * 8 + qq * 2 + half;   // this lane's score query (local)
        int s = s0 + qi;

        float score = -INFINITY;
        if (hl <= s) {
            const __half* qp = &Qs[qi * PKH];
            const __half* kp = &Ks[(qi + WW - 1 - hl) * PKH];
            float acc = 0.f;
            #pragma unroll
            for (int d = 0; d < HD; d += 8) {
                float4 qa4 = *(const float4*)(qp + d);
                float4 ka4 = *(const float4*)(kp + d);
                const __half2* qh = (const __half2*)&qa4;
                const __half2* kh = (const __half2*)&ka4;
                #pragma unroll
                for (int t = 0; t < 4; t++) {
                    float2 qf = __half22float2(qh[t]);
                    float2 kf = __half22float2(kh[t]);
                    acc = fmaf(qf.x, kf.x, acc);
                    acc = fmaf(qf.y, kf.y, acc);
                }
            }
            score = acc * 0.125f;
        }
        // 16-lane reductions (XOR < 16 stays within each half-warp)
        float mx = score;
        #pragma unroll
        for (int o = 8; o > 0; o >>= 1) mx = fmaxf(mx, __shfl_xor_sync(0xffffffffu, mx, o));
        float p = (score == -INFINITY) ? 0.f : __expf(score - mx);
        float sum = p;
        #pragma unroll
        for (int o = 8; o > 0; o >>= 1) sum += __shfl_xor_sync(0xffffffffu, sum, o);
        float inv = 1.f / sum;
        float invA = __shfl_sync(0xffffffffu, inv, 0);
        float invB = __shfl_sync(0xffffffffu, inv, 16);

        // V accumulation for both queries; lane owns dims 2*lane, 2*lane+1
        int qiA = w * 8 + qq * 2;
        int qiB = qiA + 1;
        float a0 = 0.f, a1 = 0.f, b0 = 0.f, b1 = 0.f;
        #pragma unroll
        for (int jj = 0; jj < WW; jj++) {
            float pA = __shfl_sync(0xffffffffu, p, jj);
            float pB = __shfl_sync(0xffffffffu, p, 16 + jj);
            float2 vA = __half22float2(*(const __half2*)&Vs[(qiA + WW - 1 - jj) * PKH + 2 * lane]);
            float2 vB = __half22float2(*(const __half2*)&Vs[(qiB + WW - 1 - jj) * PKH + 2 * lane]);
            a0 = fmaf(pA, vA.x, a0); a1 = fmaf(pA, vA.y, a1);
            b0 = fmaf(pB, vB.x, b0); b1 = fmaf(pB, vB.y, b1);
        }
        size_t mA = (size_t)(b * SS + s0 + qiA);
        *(__half2*)(oh + mA * DD + h * HD + 2 * lane)       = __floats2half2_rn(a0 * invA, a1 * invA);
        *(__half2*)(oh + (mA + 1) * DD + h * HD + 2 * lane) = __floats2half2_rn(b0 * invB, b1 * invB);
    }
}

// ---------------- launch ----------------
typedef CUresult (*PFN_encode)(CUtensorMap*, CUtensorMapDataType, cuuint32_t, void*,
                               const cuuint64_t*, const cuuint64_t*, const cuuint32_t*,
                               const cuuint32_t*, CUtensorMapInterleave, CUtensorMapSwizzle,
                               CUtensorMapL2promotion, CUtensorMapFloatOOBfill);

static void make_map(PFN_encode enc, CUtensorMap* m, void* ptr, uint64_t K, uint64_t R) {
    cuuint64_t dims[2]    = {K, R};
    cuuint64_t strides[1] = {K * 2};
    cuuint32_t box[2]     = {64, 128};
    cuuint32_t es[2]      = {1, 1};
    enc(m, CU_TENSOR_MAP_DATA_TYPE_FLOAT16, 2, ptr, dims, strides, box, es,
        CU_TENSOR_MAP_INTERLEAVE_NONE, CU_TENSOR_MAP_SWIZZLE_128B,
        CU_TENSOR_MAP_L2_PROMOTION_L2_128B, CU_TENSOR_MAP_FLOAT_OOB_FILL_NONE);
}

extern "C" void kernel_launch(void* const* d_in, const int* in_sizes, int n_in,
                              void* d_out, int out_size) {
    const float* x          = (const float*)d_in[0];
    const float* ln1_g      = (const float*)d_in[1];
    const float* ln1_b      = (const float*)d_in[2];
    const float* in_proj_w  = (const float*)d_in[3];
    const float* in_proj_b  = (const float*)d_in[4];
    const float* out_proj_w = (const float*)d_in[5];
    const float* out_proj_b = (const float*)d_in[6];
    const float* ln2_g      = (const float*)d_in[7];
    const float* ln2_b      = (const float*)d_in[8];
    const float* mlp_w1     = (const float*)d_in[9];
    const float* mlp_b1     = (const float*)d_in[10];
    const float* mlp_w2     = (const float*)d_in[11];
    const float* mlp_b2     = (const float*)d_in[12];
    float* out = (float*)d_out;

    float *p_x1;
    __half *p_qkvh, *p_h, *p_at, *p_xn, *p_ff, *p_wq, *p_wo, *p_w1, *p_w2;
    cudaGetSymbolAddress((void**)&p_qkvh, g_qkv_h);
    cudaGetSymbolAddress((void**)&p_x1,  g_x1);
    cudaGetSymbolAddress((void**)&p_h,   g_h_h);
    cudaGetSymbolAddress((void**)&p_at,  g_at_h);
    cudaGetSymbolAddress((void**)&p_xn,  g_xn_h);
    cudaGetSymbolAddress((void**)&p_ff,  g_ff_h);
    cudaGetSymbolAddress((void**)&p_wq,  g_wq_h);
    cudaGetSymbolAddress((void**)&p_wo,  g_wo_h);
    cudaGetSymbolAddress((void**)&p_w1,  g_w1_h);
    cudaGetSymbolAddress((void**)&p_w2,  g_w2_h);

    // driver entry point via runtime API (no -lcuda needed)
    PFN_encode enc = nullptr;
    cudaDriverEntryPointQueryResult qr;
    cudaGetDriverEntryPoint("cuTensorMapEncodeTiled", (void**)&enc,
                            cudaEnableDefault, &qr);

    CUtensorMap tm_h, tm_wq, tm_at, tm_wo, tm_xn, tm_w1, tm_ff, tm_w2;
    make_map(enc, &tm_h,  p_h,  DD,  MM);
    make_map(enc, &tm_wq, p_wq, DD,  3 * DD);
    make_map(enc, &tm_at, p_at, DD,  MM);
    make_map(enc, &tm_wo, p_wo, DD,  DD);
    make_map(enc, &tm_xn, p_xn, DD,  MM);
    make_map(enc, &tm_w1, p_w1, DD,  DFF);
    make_map(enc, &tm_ff, p_ff, DFF, MM);
    make_map(enc, &tm_w2, p_w2, DFF, DD);

    cudaFuncSetAttribute(gemmh, cudaFuncAttributeMaxDynamicSharedMemorySize, GEMM_SMEM);
    cudaFuncSetAttribute(attn_cvt_kernel, cudaFuncAttributeMaxDynamicSharedMemorySize, ATTN_SMEM);

    // LN1 rows + wq convert in one co-scheduled launch
    ln_cvt_kernel<<<MM + 3072, 256>>>(x, ln1_g, ln1_b, p_h, in_proj_w, p_wq);
    // QKV = h @ W_in^T + b -> fp16   [4096, 3072]
    gemmh<<<dim3(3 * DD / 128, MM / 128), 256, GEMM_SMEM>>>(
        tm_h, tm_wq, in_proj_b, nullptr, nullptr, p_qkvh, 3 * DD, DD, 0);
    // windowed attention + wo/w1/w2 converts co-scheduled
    attn_cvt_kernel<<<ATTN_BLOCKS + CVT_BLOCKS, 256, ATTN_SMEM>>>(
        p_qkvh, p_at, out_proj_w, p_wo, mlp_w1, p_w1, mlp_w2, p_w2);
    // out proj + residual(x) -> x1 fp32  [4096, 1024]
    gemmh<<<dim3(DD / 128, MM / 128), 256, GEMM_SMEM>>>(
        tm_at, tm_wo, out_proj_b, x, p_x1, nullptr, DD, DD, 1);
    // LN2 -> fp16
    ln_half_kernel<<<MM, 256>>>(p_x1, ln2_g, ln2_b, p_xn);
    // MLP up + GELU -> fp16   [4096, 4096]
    gemmh<<<dim3(DFF / 128, MM / 128), 256, GEMM_SMEM>>>(
        tm_xn, tm_w1, mlp_b1, nullptr, nullptr, p_ff, DFF, DD, 2);
    // MLP down + residual(x1) -> out   [4096, 1024]
    gemmh<<<dim3(DD / 128, MM / 128), 256, GEMM_SMEM>>>(
        tm_ff, tm_w2, mlp_b2, p_x1, out, nullptr, DD, DFF, 1);
}

// round 16
// speedup vs baseline: 1.4061x; 1.4061x over previous
#include <cuda_runtime.h>
#include <cuda.h>
#include <cuda_fp16.h>
#include <math.h>
#include <stdint.h>

// Problem constants
#define BB 2
#define SS 2048
#define DD 1024
#define HH 16
#define HD 64
#define WW 16
#define DFF 4096
#define MM (BB * SS)   // 4096 rows

// ---------------- scratch (no allocations allowed) ----------------
__device__ __half g_qkv_h[MM * 3 * DD];       // QKV fp16
__device__ float g_x1[MM * DD];               // residual-1 output fp32
__device__ __half g_h_h[MM * DD];             // LN1 out fp16
__device__ __half g_at_h[MM * DD];            // attn out fp16
__device__ __half g_xn_h[MM * DD];            // LN2 out fp16
__device__ __half g_ff_h[MM * DFF];           // MLP hidden fp16
__device__ __half g_wq_h[3 * DD * DD];
__device__ __half g_wo_h[DD * DD];
__device__ __half g_w1_h[DFF * DD];
__device__ __half g_w2_h[DD * DFF];

__device__ __forceinline__ uint32_t smem_u32(const void* p) {
    return (uint32_t)__cvta_generic_to_shared(p);
}

__device__ __forceinline__ float gelu_tanh(float x) {
    float x3 = x * x * x;
    return 0.5f * x * (1.0f + tanhf(0.7978845608028654f * (x + 0.044715f * x3)));
}

// ---------------- weight convert kernel (fp32 -> fp16, 4 segments) ----------------
__global__ void cvt4_kernel(const float* __restrict__ wq, __half* __restrict__ owq,
                            const float* __restrict__ wo, __half* __restrict__ owo,
                            const float* __restrict__ w1, __half* __restrict__ ow1,
                            const float* __restrict__ w2, __half* __restrict__ ow2) {
    int blk = blockIdx.x;
    const float* in; __half* out; int base;
    if (blk < 3072)       { in = wq; out = owq; base = blk; }
    else if (blk < 4096)  { in = wo; out = owo; base = blk - 3072; }
    else if (blk < 8192)  { in = w1; out = ow1; base = blk - 4096; }
    else                  { in = w2; out = ow2; base = blk - 8192; }
    int i = base * 1024 + threadIdx.x * 4;
    float4 v = *(const float4*)(in + i);
    *(__half2*)(out + i)     = __floats2half2_rn(v.x, v.y);
    *(__half2*)(out + i + 2) = __floats2half2_rn(v.z, v.w);
}

// ---------------- LayerNorm -> fp16 ----------------
__global__ void ln_half_kernel(const float* __restrict__ x,
                               const float* __restrict__ g,
                               const float* __restrict__ b,
                               __half* __restrict__ y) {
    int row = blockIdx.x;
    const float* xp = x + (size_t)row * DD;
    int i = threadIdx.x * 4;
    float4 xv = *(const float4*)(xp + i);
    float s  = xv.x + xv.y + xv.z + xv.w;
    float ss = xv.x*xv.x + xv.y*xv.y + xv.z*xv.z + xv.w*xv.w;
    for (int o = 16; o > 0; o >>= 1) {
        s  += __shfl_xor_sync(0xffffffffu, s,  o);
        ss += __shfl_xor_sync(0xffffffffu, ss, o);
    }
    __shared__ float sh_s[8], sh_ss[8];
    int wid = threadIdx.x >> 5, lane = threadIdx.x & 31;
    if (lane == 0) { sh_s[wid] = s; sh_ss[wid] = ss; }
    __syncthreads();
    if (wid == 0) {
        s  = (lane < 8) ? sh_s[lane]  : 0.f;
        ss = (lane < 8) ? sh_ss[lane] : 0.f;
        for (int o = 4; o > 0; o >>= 1) {
            s  += __shfl_xor_sync(0xffffffffu, s,  o);
            ss += __shfl_xor_sync(0xffffffffu, ss, o);
        }
        if (lane == 0) { sh_s[0] = s; sh_ss[0] = ss; }
    }
    __syncthreads();
    float mean = sh_s[0] * (1.0f / DD);
    float var  = sh_ss[0] * (1.0f / DD) - mean * mean;
    float inv  = rsqrtf(var + 1e-5f);
    float4 gv = *(const float4*)(g + i);
    float4 bv = *(const float4*)(b + i);
    float o0 = (xv.x - mean) * inv * gv.x + bv.x;
    float o1 = (xv.y - mean) * inv * gv.y + bv.y;
    float o2 = (xv.z - mean) * inv * gv.z + bv.z;
    float o3 = (xv.w - mean) * inv * gv.w + bv.w;
    size_t idx = (size_t)row * DD + i;
    *(__half2*)(y + idx)     = __floats2half2_rn(o0, o1);
    *(__half2*)(y + idx + 2) = __floats2half2_rn(o2, o3);
}

// ---------------- TMA + mma.sync fp16 GEMM: C[M,N] = A[M,K] @ Bw[N,K]^T (+epi) ----------------
// BM=256 x BN=128 tile (512 threads, 16 warps) to cut L2 tile traffic 25%
// (MLP2 measured at the 11.1 TB/s LTS cap with 128x128 tiles).
// 3-stage TMA pipeline, full/empty mbarriers, fence.proxy.async cross-proxy safety.
// Tile bases MUST be 1024B-aligned so the manual swizzle matches TMA's.
// epi: 0 = +bias -> fp16 ; 1 = fp32 +bias+res ; 2 = gelu(+bias) -> fp16
#define BKT 64
#define A_TILE_BYTES (256 * 128)        // 32768 (256 rows x 64 fp16)
#define B_TILE_BYTES (128 * 128)        // 16384 (128 rows x 64 fp16)
#define OFF_A 0
#define OFF_B A_TILE_BYTES
#define STAGE_BYTES (A_TILE_BYTES + B_TILE_BYTES)   // 49152 (1024-multiple)
#define NSTAGE 3
#define GEMM_SMEM (NSTAGE * STAGE_BYTES + 1024)     // 148480

#define LDMX4(r0, r1, r2, r3, addr) \
    asm volatile("ldmatrix.sync.aligned.m8n8.x4.shared.b16 {%0,%1,%2,%3}, [%4];" \
                 : "=r"(r0), "=r"(r1), "=r"(r2), "=r"(r3) : "r"(addr))

#define MMA_F16(d, a, b0, b1) \
    asm volatile("mma.sync.aligned.m16n8k16.row.col.f32.f16.f16.f32 " \
                 "{%0,%1,%2,%3}, {%4,%5,%6,%7}, {%8,%9}, {%0,%1,%2,%3};" \
                 : "+f"((d)[0]), "+f"((d)[1]), "+f"((d)[2]), "+f"((d)[3]) \
                 : "r"((a)[0]), "r"((a)[1]), "r"((a)[2]), "r"((a)[3]), "r"(b0), "r"(b1))

#define MBAR_INIT(mbar, cnt) \
    asm volatile("mbarrier.init.shared.b64 [%0], %1;" :: "r"(mbar), "r"(cnt) : "memory")

#define MBAR_EXPECT(mbar, bytes) \
    asm volatile("mbarrier.arrive.expect_tx.shared.b64 _, [%0], %1;" :: "r"(mbar), "r"(bytes) : "memory")

#define MBAR_ARRIVE(mbar) \
    asm volatile("mbarrier.arrive.release.cta.shared::cta.b64 _, [%0];" :: "r"(mbar) : "memory")

#define FENCE_ASYNC() \
    asm volatile("fence.proxy.async.shared::cta;" ::: "memory")

#define MBAR_WAIT(mbar, parity) do {                                            \
    uint32_t _m = (mbar); uint32_t _p = (parity); uint32_t _d;                  \
    asm volatile("{\n\t.reg .pred p;\n\t"                                       \
        "mbarrier.try_wait.parity.acquire.cta.shared::cta.b64 p, [%1], %2;\n\t" \
        "selp.b32 %0, 1, 0, p;\n\t}"                                            \
        : "=r"(_d) : "r"(_m), "r"(_p) : "memory");                              \
    if (!_d) {                                                                  \
        asm volatile("{\n\t.reg .pred P1;\n\t"                                  \
            "WL_%=:\n\t"                                                        \
            "mbarrier.try_wait.parity.acquire.cta.shared::cta.b64 P1, [%0], %1, 0x989680;\n\t" \
            "@P1 bra.uni WD_%=;\n\t"                                            \
            "bra.uni WL_%=;\n\t"                                                \
            "WD_%=:\n\t}" :: "r"(_m), "r"(_p) : "memory");                      \
    }                                                                           \
} while (0)

#define TMA_LD2D(smem, tmap, cx, cy, mbar) \
    asm volatile("cp.async.bulk.tensor.2d.shared::cta.global.tile.mbarrier::complete_tx::bytes " \
                 "[%0], [%1, {%2, %3}], [%4];" \
                 :: "r"(smem), "l"(tmap), "r"(cx), "r"(cy), "r"(mbar) : "memory")

// swizzled byte offset inside a 128B-row SW128 tile: row r, 16B unit u (0..7)
// valid ONLY when tile base is 1024B-aligned (pattern repeats every 8 rows)
__device__ __forceinline__ uint32_t sw_off(int r, int u) {
    return (uint32_t)(r * 128 + ((u ^ (r & 7)) << 4));
}

__global__ __launch_bounds__(512, 1)
void gemmh(const __grid_constant__ CUtensorMap tmA,
           const __grid_constant__ CUtensorMap tmB,
           const float* __restrict__ bias, const float* __restrict__ res,
           float* __restrict__ outF, __half* __restrict__ outH,
           int Nn, int Kk, int epi) {
    extern __shared__ __align__(128) char dsm[];
    __shared__ __align__(8) uint64_t s_full[NSTAGE];
    __shared__ __align__(8) uint64_t s_empty[NSTAGE];
    uint32_t sbase = (smem_u32(dsm) + 1023) & ~1023u;   // 1024B-align: swizzle phase contract
    int tid = threadIdx.x;
    int lane = tid & 31;
    int wid = tid >> 5;      // 0..15
    int wr = wid & 3;        // warp row: m offset wr*64
    int wc = wid >> 2;       // warp col: n offset wc*32
    int bm = blockIdx.y * 256;
    int bn = blockIdx.x * 128;

    float acc[4][4][4];
    #pragma unroll
    for (int mi = 0; mi < 4; mi++)
        #pragma unroll
        for (int ni = 0; ni < 4; ni++)
            #pragma unroll
            for (int q = 0; q < 4; q++) acc[mi][ni][q] = 0.f;

    const int NC = Kk >> 6;   // BKT=64 chunks

    if (tid == 0) {
        #pragma unroll
        for (int s = 0; s < NSTAGE; s++) {
            MBAR_INIT(smem_u32(&s_full[s]), 1);
            MBAR_INIT(smem_u32(&s_empty[s]), 16);   // one arrive per warp
        }
    }
    __syncthreads();

    // prologue: issue chunks 0, 1
    if (tid == 0) {
        FENCE_ASYNC();   // order barrier inits (generic) before async-proxy use
        #pragma unroll
        for (int c0 = 0; c0 < 2; c0++) {
            if (c0 < NC) {
                uint32_t st = sbase + c0 * STAGE_BYTES;
                uint32_t mb = smem_u32(&s_full[c0]);
                MBAR_EXPECT(mb, STAGE_BYTES);
                TMA_LD2D(st + OFF_A, &tmA, c0 << 6, bm, mb);
                TMA_LD2D(st + OFF_B, &tmB, c0 << 6, bn, mb);
            }
        }
    }

    int a_row = wr * 64 + (lane & 15);
    int a_usel = (lane >> 4) & 1;
    int b_row = wc * 32 + (lane & 7) + ((lane >> 4) & 1) * 8;
    int b_usel = (lane >> 3) & 1;

    for (int c = 0; c < NC; c++) {
        int stg = c % NSTAGE;
        MBAR_WAIT(smem_u32(&s_full[stg]), (c / NSTAGE) & 1);

        uint32_t st = sbase + stg * STAGE_BYTES;
        #pragma unroll
        for (int kk = 0; kk < 4; kk++) {
            uint32_t bh[8];
            #pragma unroll
            for (int g = 0; g < 2; g++) {
                int r = b_row + g * 16;
                uint32_t off = sw_off(r, kk * 2 + b_usel);
                LDMX4(bh[g*4+0], bh[g*4+1], bh[g*4+2], bh[g*4+3], st + OFF_B + off);
            }
            #pragma unroll
            for (int mi = 0; mi < 4; mi++) {
                uint32_t ah[4];
                int r = a_row + mi * 16;
                uint32_t off = sw_off(r, kk * 2 + a_usel);
                LDMX4(ah[0], ah[1], ah[2], ah[3], st + OFF_A + off);
                #pragma unroll
                for (int ni = 0; ni < 4; ni++) {
                    MMA_F16(acc[mi][ni], ah, bh[ni*2], bh[ni*2+1]);
                }
            }
        }
        // warp done with this stage's smem (LDSM is warp-synchronous -> lane0 release is sound)
        if (lane == 0) MBAR_ARRIVE(smem_u32(&s_empty[stg]));

        if (tid == 0 && c + 2 < NC) {
            int cn = c + 2;
            int sn = cn % NSTAGE;
            if (cn >= NSTAGE)
                MBAR_WAIT(smem_u32(&s_empty[sn]), (cn / NSTAGE - 1) & 1);
            // order all consumers' generic-proxy reads before the async-proxy TMA write
            FENCE_ASYNC();
            uint32_t st2 = sbase + sn * STAGE_BYTES;
            uint32_t mb = smem_u32(&s_full[sn]);
            MBAR_EXPECT(mb, STAGE_BYTES);
            TMA_LD2D(st2 + OFF_A, &tmA, cn << 6, bm, mb);
            TMA_LD2D(st2 + OFF_B, &tmB, cn << 6, bn, mb);
        }
    }

    // epilogue
    int m0 = bm + wr * 64 + (lane >> 2);
    int n0 = bn + wc * 32 + (lane & 3) * 2;
    #pragma unroll
    for (int mi = 0; mi < 4; mi++) {
        #pragma unroll
        for (int r2 = 0; r2 < 2; r2++) {
            int row = m0 + mi * 16 + r2 * 8;
            size_t rbase = (size_t)row * Nn;
            #pragma unroll
            for (int ni = 0; ni < 4; ni++) {
                int col = n0 + ni * 8;
                float v0 = acc[mi][ni][r2*2+0] + bias[col];
                float v1 = acc[mi][ni][r2*2+1] + bias[col+1];
                if (epi == 0) {
                    *(__half2*)(outH + rbase + col) = __floats2half2_rn(v0, v1);
                } else if (epi == 1) {
                    float2 rv = *(const float2*)(res + rbase + col);
                    *(float2*)(outF + rbase + col) = make_float2(v0 + rv.x, v1 + rv.y);
                } else {
                    v0 = gelu_tanh(v0); v1 = gelu_tanh(v1);
                    *(__half2*)(outH + rbase + col) = __floats2half2_rn(v0, v1);
                }
            }
        }
    }
}

// ---------------- Sliding-window causal attention (W=16), fp16, dual-query warps ----------------
// Lanes 0-15 score query A, lanes 16-31 score query B. Q, K, V staged in smem.
#define TQ 64
#define KR (TQ + WW - 1)     // 79 key rows
#define PKH 72               // halves per smem row (144B, 16B-aligned rows)
#define ATTN_SMEM ((2 * 80 + 64) * PKH * 2)   // K + V + Q = 32256 bytes

__global__ __launch_bounds__(256, 6)
void attn_kernel(const __half* __restrict__ qkv,
                 __half* __restrict__ oh) {
    extern __shared__ __align__(16) __half asm_h[];
    __half* Ks = asm_h;                 // [80][PKH]
    __half* Vs = asm_h + 80 * PKH;      // [80][PKH]
    __half* Qs = asm_h + 160 * PKH;     // [64][PKH]

    int tile = blockIdx.x;
    int h = blockIdx.y;
    int b = blockIdx.z;
    int s0 = tile * TQ;
    int tid = threadIdx.x;
    int lane = tid & 31;
    int w = tid >> 5;

    // cooperative K/V load: 79 rows x 64 halves, 16B chunks; zero-fill seq<0 rows
    for (int i = tid; i < KR * (HD / 8); i += 256) {
        int r = i >> 3;
        int c = (i & 7) * 8;
        int seq = s0 - (WW - 1) + r;
        if (seq >= 0) {
            size_t base = ((size_t)(b * SS + seq)) * (3 * DD) + h * HD + c;
            *(float4*)&Ks[r * PKH + c] = *(const float4*)(qkv + base + DD);
            *(float4*)&Vs[r * PKH + c] = *(const float4*)(qkv + base + 2 * DD);
        } else {
            float4 z = make_float4(0.f, 0.f, 0.f, 0.f);
            *(float4*)&Ks[r * PKH + c] = z;
            *(float4*)&Vs[r * PKH + c] = z;
        }
    }
    // cooperative Q load: 64 rows x 64 halves
    for (int i = tid; i < TQ * (HD / 8); i += 256) {
        int r = i >> 3;
        int c = (i & 7) * 8;
        size_t base = ((size_t)(b * SS + s0 + r)) * (3 * DD) + h * HD + c;
        *(float4*)&Qs[r * PKH + c] = *(const float4*)(qkv + base);
    }
    __syncthreads();

    int half = lane >> 4;   // 0: query A, 1: query B
    int hl = lane & 15;     // key offset j for the score phase

    for (int qq = 0; qq < 4; qq++) {
        int qi = w * 8 + qq * 2 + half;   // this lane's score query (local)
        int s = s0 + qi;

        float score = -INFINITY;
        if (hl <= s) {
            const __half* qp = &Qs[qi * PKH];
            const __half* kp = &Ks[(qi + WW - 1 - hl) * PKH];
            float acc = 0.f;
            #pragma unroll
            for (int d = 0; d < HD; d += 8) {
                float4 qa4 = *(const float4*)(qp + d);
                float4 ka4 = *(const float4*)(kp + d);
                const __half2* qh = (const __half2*)&qa4;
                const __half2* kh = (const __half2*)&ka4;
                #pragma unroll
                for (int t = 0; t < 4; t++) {
                    float2 qf = __half22float2(qh[t]);
                    float2 kf = __half22float2(kh[t]);
                    acc = fmaf(qf.x, kf.x, acc);
                    acc = fmaf(qf.y, kf.y, acc);
                }
            }
            score = acc * 0.125f;
        }
        // 16-lane reductions (XOR < 16 stays within each half-warp)
        float mx = score;
        #pragma unroll
        for (int o = 8; o > 0; o >>= 1) mx = fmaxf(mx, __shfl_xor_sync(0xffffffffu, mx, o));
        float p = (score == -INFINITY) ? 0.f : __expf(score - mx);
        float sum = p;
        #pragma unroll
        for (int o = 8; o > 0; o >>= 1) sum += __shfl_xor_sync(0xffffffffu, sum, o);
        float inv = 1.f / sum;
        float invA = __shfl_sync(0xffffffffu, inv, 0);
        float invB = __shfl_sync(0xffffffffu, inv, 16);

        // V accumulation for both queries; lane owns dims 2*lane, 2*lane+1
        int qiA = w * 8 + qq * 2;
        int qiB = qiA + 1;
        float a0 = 0.f, a1 = 0.f, b0 = 0.f, b1 = 0.f;
        #pragma unroll
        for (int jj = 0; jj < WW; jj++) {
            float pA = __shfl_sync(0xffffffffu, p, jj);
            float pB = __shfl_sync(0xffffffffu, p, 16 + jj);
            float2 vA = __half22float2(*(const __half2*)&Vs[(qiA + WW - 1 - jj) * PKH + 2 * lane]);
            float2 vB = __half22float2(*(const __half2*)&Vs[(qiB + WW - 1 - jj) * PKH + 2 * lane]);
            a0 = fmaf(pA, vA.x, a0); a1 = fmaf(pA, vA.y, a1);
            b0 = fmaf(pB, vB.x, b0); b1 = fmaf(pB, vB.y, b1);
        }
        size_t mA = (size_t)(b * SS + s0 + qiA);
        *(__half2*)(oh + mA * DD + h * HD + 2 * lane)       = __floats2half2_rn(a0 * invA, a1 * invA);
        *(__half2*)(oh + (mA + 1) * DD + h * HD + 2 * lane) = __floats2half2_rn(b0 * invB, b1 * invB);
    }
}

// ---------------- launch ----------------
typedef CUresult (*PFN_encode)(CUtensorMap*, CUtensorMapDataType, cuuint32_t, void*,
                               const cuuint64_t*, const cuuint64_t*, const cuuint32_t*,
                               const cuuint32_t*, CUtensorMapInterleave, CUtensorMapSwizzle,
                               CUtensorMapL2promotion, CUtensorMapFloatOOBfill);

static void make_map(PFN_encode enc, CUtensorMap* m, void* ptr, uint64_t K, uint64_t R,
                     uint32_t box_r) {
    cuuint64_t dims[2]    = {K, R};
    cuuint64_t strides[1] = {K * 2};
    cuuint32_t box[2]     = {64, box_r};
    cuuint32_t es[2]      = {1, 1};
    enc(m, CU_TENSOR_MAP_DATA_TYPE_FLOAT16, 2, ptr, dims, strides, box, es,
        CU_TENSOR_MAP_INTERLEAVE_NONE, CU_TENSOR_MAP_SWIZZLE_128B,
        CU_TENSOR_MAP_L2_PROMOTION_L2_128B, CU_TENSOR_MAP_FLOAT_OOB_FILL_NONE);
}

extern "C" void kernel_launch(void* const* d_in, const int* in_sizes, int n_in,
                              void* d_out, int out_size) {
    const float* x          = (const float*)d_in[0];
    const float* ln1_g      = (const float*)d_in[1];
    const float* ln1_b      = (const float*)d_in[2];
    const float* in_proj_w  = (const float*)d_in[3];
    const float* in_proj_b  = (const float*)d_in[4];
    const float* out_proj_w = (const float*)d_in[5];
    const float* out_proj_b = (const float*)d_in[6];
    const float* ln2_g      = (const float*)d_in[7];
    const float* ln2_b      = (const float*)d_in[8];
    const float* mlp_w1     = (const float*)d_in[9];
    const float* mlp_b1     = (const float*)d_in[10];
    const float* mlp_w2     = (const float*)d_in[11];
    const float* mlp_b2     = (const float*)d_in[12];
    float* out = (float*)d_out;

    float *p_x1;
    __half *p_qkvh, *p_h, *p_at, *p_xn, *p_ff, *p_wq, *p_wo, *p_w1, *p_w2;
    cudaGetSymbolAddress((void**)&p_qkvh, g_qkv_h);
    cudaGetSymbolAddress((void**)&p_x1,  g_x1);
    cudaGetSymbolAddress((void**)&p_h,   g_h_h);
    cudaGetSymbolAddress((void**)&p_at,  g_at_h);
    cudaGetSymbolAddress((void**)&p_xn,  g_xn_h);
    cudaGetSymbolAddress((void**)&p_ff,  g_ff_h);
    cudaGetSymbolAddress((void**)&p_wq,  g_wq_h);
    cudaGetSymbolAddress((void**)&p_wo,  g_wo_h);
    cudaGetSymbolAddress((void**)&p_w1,  g_w1_h);
    cudaGetSymbolAddress((void**)&p_w2,  g_w2_h);

    // driver entry point via runtime API (no -lcuda needed)
    PFN_encode enc = nullptr;
    cudaDriverEntryPointQueryResult qr;
    cudaGetDriverEntryPoint("cuTensorMapEncodeTiled", (void**)&enc,
                            cudaEnableDefault, &qr);

    // A operands: 256-row boxes; B operands (weights): 128-row boxes
    CUtensorMap tm_h, tm_wq, tm_at, tm_wo, tm_xn, tm_w1, tm_ff, tm_w2;
    make_map(enc, &tm_h,  p_h,  DD,  MM,     256);
    make_map(enc, &tm_wq, p_wq, DD,  3 * DD, 128);
    make_map(enc, &tm_at, p_at, DD,  MM,     256);
    make_map(enc, &tm_wo, p_wo, DD,  DD,     128);
    make_map(enc, &tm_xn, p_xn, DD,  MM,     256);
    make_map(enc, &tm_w1, p_w1, DD,  DFF,    128);
    make_map(enc, &tm_ff, p_ff, DFF, MM,     256);
    make_map(enc, &tm_w2, p_w2, DFF, DD,     128);

    cudaFuncSetAttribute(gemmh, cudaFuncAttributeMaxDynamicSharedMemorySize, GEMM_SMEM);
    cudaFuncSetAttribute(attn_kernel, cudaFuncAttributeMaxDynamicSharedMemorySize, ATTN_SMEM);

    cvt4_kernel<<<12288, 256>>>(in_proj_w, p_wq, out_proj_w, p_wo,
                                mlp_w1, p_w1, mlp_w2, p_w2);
    ln_half_kernel<<<MM, 256>>>(x, ln1_g, ln1_b, p_h);
    // QKV = h @ W_in^T + b -> fp16   [4096, 3072]
    gemmh<<<dim3(3 * DD / 128, MM / 256), 512, GEMM_SMEM>>>(
        tm_h, tm_wq, in_proj_b, nullptr, nullptr, p_qkvh, 3 * DD, DD, 0);
    // windowed attention (fp16 smem-tiled, dual-query, Q/K/V smem) -> fp16
    attn_kernel<<<dim3(SS / TQ, HH, BB), 256, ATTN_SMEM>>>(p_qkvh, p_at);
    // out proj + residual(x) -> x1 fp32  [4096, 1024]
    gemmh<<<dim3(DD / 128, MM / 256), 512, GEMM_SMEM>>>(
        tm_at, tm_wo, out_proj_b, x, p_x1, nullptr, DD, DD, 1);
    // LN2 -> fp16
    ln_half_kernel<<<MM, 256>>>(p_x1, ln2_g, ln2_b, p_xn);
    // MLP up + GELU -> fp16   [4096, 4096]
    gemmh<<<dim3(DFF / 128, MM / 256), 512, GEMM_SMEM>>>(
        tm_xn, tm_w1, mlp_b1, nullptr, nullptr, p_ff, DFF, DD, 2);
    // MLP down + residual(x1) -> out   [4096, 1024]
    gemmh<<<dim3(DD / 128, MM / 256), 512, GEMM_SMEM>>>(
        tm_ff, tm_w2, mlp_b2, p_x1, out, nullptr, DD, DFF, 1);
}

// round 17
// speedup vs baseline: 1.4820x; 1.0540x over previous
#include <cuda_runtime.h>
#include <cuda.h>
#include <cuda_fp16.h>
#include <math.h>
#include <stdint.h>

// Problem constants
#define BB 2
#define SS 2048
#define DD 1024
#define HH 16
#define HD 64
#define WW 16
#define DFF 4096
#define MM (BB * SS)   // 4096 rows

// ---------------- scratch (no allocations allowed) ----------------
__device__ __half g_qkv_h[MM * 3 * DD];       // QKV fp16
__device__ __half g_x1_h[MM * DD];            // residual-1 output fp16
__device__ __half g_h_h[MM * DD];             // LN1 out fp16
__device__ __half g_at_h[MM * DD];            // attn out fp16
__device__ __half g_xn_h[MM * DD];            // LN2 out fp16
__device__ __half g_ff_h[MM * DFF];           // MLP hidden fp16
__device__ __half g_wq_h[3 * DD * DD];
__device__ __half g_wo_h[DD * DD];
__device__ __half g_w1_h[DFF * DD];
__device__ __half g_w2_h[DD * DFF];

__device__ __forceinline__ uint32_t smem_u32(const void* p) {
    return (uint32_t)__cvta_generic_to_shared(p);
}

__device__ __forceinline__ float gelu_tanh(float x) {
    float x3 = x * x * x;
    return 0.5f * x * (1.0f + tanhf(0.7978845608028654f * (x + 0.044715f * x3)));
}

// ---------------- weight convert kernel (fp32 -> fp16, 4 segments) ----------------
__global__ void cvt4_kernel(const float* __restrict__ wq, __half* __restrict__ owq,
                            const float* __restrict__ wo, __half* __restrict__ owo,
                            const float* __restrict__ w1, __half* __restrict__ ow1,
                            const float* __restrict__ w2, __half* __restrict__ ow2) {
    int blk = blockIdx.x;
    const float* in; __half* out; int base;
    if (blk < 3072)       { in = wq; out = owq; base = blk; }
    else if (blk < 4096)  { in = wo; out = owo; base = blk - 3072; }
    else if (blk < 8192)  { in = w1; out = ow1; base = blk - 4096; }
    else                  { in = w2; out = ow2; base = blk - 8192; }
    int i = base * 1024 + threadIdx.x * 4;
    float4 v = *(const float4*)(in + i);
    *(__half2*)(out + i)     = __floats2half2_rn(v.x, v.y);
    *(__half2*)(out + i + 2) = __floats2half2_rn(v.z, v.w);
}

// ---------------- LayerNorm (fp32 in) -> fp16 ----------------
__global__ void ln_half_kernel(const float* __restrict__ x,
                               const float* __restrict__ g,
                               const float* __restrict__ b,
                               __half* __restrict__ y) {
    int row = blockIdx.x;
    const float* xp = x + (size_t)row * DD;
    int i = threadIdx.x * 4;
    float4 xv = *(const float4*)(xp + i);
    float s  = xv.x + xv.y + xv.z + xv.w;
    float ss = xv.x*xv.x + xv.y*xv.y + xv.z*xv.z + xv.w*xv.w;
    for (int o = 16; o > 0; o >>= 1) {
        s  += __shfl_xor_sync(0xffffffffu, s,  o);
        ss += __shfl_xor_sync(0xffffffffu, ss, o);
    }
    __shared__ float sh_s[8], sh_ss[8];
    int wid = threadIdx.x >> 5, lane = threadIdx.x & 31;
    if (lane == 0) { sh_s[wid] = s; sh_ss[wid] = ss; }
    __syncthreads();
    if (wid == 0) {
        s  = (lane < 8) ? sh_s[lane]  : 0.f;
        ss = (lane < 8) ? sh_ss[lane] : 0.f;
        for (int o = 4; o > 0; o >>= 1) {
            s  += __shfl_xor_sync(0xffffffffu, s,  o);
            ss += __shfl_xor_sync(0xffffffffu, ss, o);
        }
        if (lane == 0) { sh_s[0] = s; sh_ss[0] = ss; }
    }
    __syncthreads();
    float mean = sh_s[0] * (1.0f / DD);
    float var  = sh_ss[0] * (1.0f / DD) - mean * mean;
    float inv  = rsqrtf(var + 1e-5f);
    float4 gv = *(const float4*)(g + i);
    float4 bv = *(const float4*)(b + i);
    float o0 = (xv.x - mean) * inv * gv.x + bv.x;
    float o1 = (xv.y - mean) * inv * gv.y + bv.y;
    float o2 = (xv.z - mean) * inv * gv.z + bv.z;
    float o3 = (xv.w - mean) * inv * gv.w + bv.w;
    size_t idx = (size_t)row * DD + i;
    *(__half2*)(y + idx)     = __floats2half2_rn(o0, o1);
    *(__half2*)(y + idx + 2) = __floats2half2_rn(o2, o3);
}

// ---------------- LayerNorm (fp16 in) -> fp16 ----------------
__global__ void ln_half_in_kernel(const __half* __restrict__ x,
                                  const float* __restrict__ g,
                                  const float* __restrict__ b,
                                  __half* __restrict__ y) {
    int row = blockIdx.x;
    int i = threadIdx.x * 4;
    const __half2* xp2 = (const __half2*)(x + (size_t)row * DD + i);
    float2 xa = __half22float2(xp2[0]);
    float2 xb = __half22float2(xp2[1]);
    float s  = xa.x + xa.y + xb.x + xb.y;
    float ss = xa.x*xa.x + xa.y*xa.y + xb.x*xb.x + xb.y*xb.y;
    for (int o = 16; o > 0; o >>= 1) {
        s  += __shfl_xor_sync(0xffffffffu, s,  o);
        ss += __shfl_xor_sync(0xffffffffu, ss, o);
    }
    __shared__ float sh_s[8], sh_ss[8];
    int wid = threadIdx.x >> 5, lane = threadIdx.x & 31;
    if (lane == 0) { sh_s[wid] = s; sh_ss[wid] = ss; }
    __syncthreads();
    if (wid == 0) {
        s  = (lane < 8) ? sh_s[lane]  : 0.f;
        ss = (lane < 8) ? sh_ss[lane] : 0.f;
        for (int o = 4; o > 0; o >>= 1) {
            s  += __shfl_xor_sync(0xffffffffu, s,  o);
            ss += __shfl_xor_sync(0xffffffffu, ss, o);
        }
        if (lane == 0) { sh_s[0] = s; sh_ss[0] = ss; }
    }
    __syncthreads();
    float mean = sh_s[0] * (1.0f / DD);
    float var  = sh_ss[0] * (1.0f / DD) - mean * mean;
    float inv  = rsqrtf(var + 1e-5f);
    float4 gv = *(const float4*)(g + i);
    float4 bv = *(const float4*)(b + i);
    float o0 = (xa.x - mean) * inv * gv.x + bv.x;
    float o1 = (xa.y - mean) * inv * gv.y + bv.y;
    float o2 = (xb.x - mean) * inv * gv.z + bv.z;
    float o3 = (xb.y - mean) * inv * gv.w + bv.w;
    size_t idx = (size_t)row * DD + i;
    *(__half2*)(y + idx)     = __floats2half2_rn(o0, o1);
    *(__half2*)(y + idx + 2) = __floats2half2_rn(o2, o3);
}

// ---------------- TMA + mma.sync fp16 GEMM: C[M,N] = A[M,K] @ Bw[N,K]^T (+epi) ----------------
// 128x128 tile, 256 threads, 2 CTA/SM (proven R14 geometry).
// 3-stage TMA pipeline, full/empty mbarriers; lane0-only empty arrives (count 8).
// fence.proxy.async orders generic-proxy smem reads before async-proxy TMA overwrite.
// Tile bases MUST be 1024B-aligned so the manual swizzle matches TMA's.
// epi: 0 = +bias -> fp16 ; 2 = gelu(+bias) -> fp16 ;
//      3 = +bias + fp32 res -> fp16 ; 4 = +bias + fp16 res -> fp32
#define BKT 64
#define TILE_BYTES (128 * 128)          // 16384 (64 fp16 = 128 B per row)
#define OFF_A 0
#define OFF_B TILE_BYTES
#define STAGE_BYTES (2 * TILE_BYTES)    // 32768
#define NSTAGE 3
#define GEMM_SMEM (NSTAGE * STAGE_BYTES + 1024)  // 99328 (1KB alignment slack)

#define LDMX4(r0, r1, r2, r3, addr) \
    asm volatile("ldmatrix.sync.aligned.m8n8.x4.shared.b16 {%0,%1,%2,%3}, [%4];" \
                 : "=r"(r0), "=r"(r1), "=r"(r2), "=r"(r3) : "r"(addr))

#define MMA_F16(d, a, b0, b1) \
    asm volatile("mma.sync.aligned.m16n8k16.row.col.f32.f16.f16.f32 " \
                 "{%0,%1,%2,%3}, {%4,%5,%6,%7}, {%8,%9}, {%0,%1,%2,%3};" \
                 : "+f"((d)[0]), "+f"((d)[1]), "+f"((d)[2]), "+f"((d)[3]) \
                 : "r"((a)[0]), "r"((a)[1]), "r"((a)[2]), "r"((a)[3]), "r"(b0), "r"(b1))

#define MBAR_INIT(mbar, cnt) \
    asm volatile("mbarrier.init.shared.b64 [%0], %1;" :: "r"(mbar), "r"(cnt) : "memory")

#define MBAR_EXPECT(mbar, bytes) \
    asm volatile("mbarrier.arrive.expect_tx.shared.b64 _, [%0], %1;" :: "r"(mbar), "r"(bytes) : "memory")

#define MBAR_ARRIVE(mbar) \
    asm volatile("mbarrier.arrive.release.cta.shared::cta.b64 _, [%0];" :: "r"(mbar) : "memory")

#define FENCE_ASYNC() \
    asm volatile("fence.proxy.async.shared::cta;" ::: "memory")

#define MBAR_WAIT(mbar, parity) do {                                            \
    uint32_t _m = (mbar); uint32_t _p = (parity); uint32_t _d;                  \
    asm volatile("{\n\t.reg .pred p;\n\t"                                       \
        "mbarrier.try_wait.parity.acquire.cta.shared::cta.b64 p, [%1], %2;\n\t" \
        "selp.b32 %0, 1, 0, p;\n\t}"                                            \
        : "=r"(_d) : "r"(_m), "r"(_p) : "memory");                              \
    if (!_d) {                                                                  \
        asm volatile("{\n\t.reg .pred P1;\n\t"                                  \
            "WL_%=:\n\t"                                                        \
            "mbarrier.try_wait.parity.acquire.cta.shared::cta.b64 P1, [%0], %1, 0x989680;\n\t" \
            "@P1 bra.uni WD_%=;\n\t"                                            \
            "bra.uni WL_%=;\n\t"                                                \
            "WD_%=:\n\t}" :: "r"(_m), "r"(_p) : "memory");                      \
    }                                                                           \
} while (0)

#define TMA_LD2D(smem, tmap, cx, cy, mbar) \
    asm volatile("cp.async.bulk.tensor.2d.shared::cta.global.tile.mbarrier::complete_tx::bytes " \
                 "[%0], [%1, {%2, %3}], [%4];" \
                 :: "r"(smem), "l"(tmap), "r"(cx), "r"(cy), "r"(mbar) : "memory")

// swizzled byte offset inside one 128x64(fp16) tile: row r (0..127), 16B unit u (0..7)
// valid ONLY when tile base is 1024B-aligned
__device__ __forceinline__ uint32_t sw_off(int r, int u) {
    return (uint32_t)(r * 128 + ((u ^ (r & 7)) << 4));
}

__global__ __launch_bounds__(256, 2)
void gemmh(const __grid_constant__ CUtensorMap tmA,
           const __grid_constant__ CUtensorMap tmB,
           const float* __restrict__ bias,
           const float* __restrict__ resF, const __half* __restrict__ resH,
           float* __restrict__ outF, __half* __restrict__ outH,
           int Nn, int Kk, int epi) {
    extern __shared__ __align__(128) char dsm[];
    __shared__ __align__(8) uint64_t s_full[NSTAGE];
    __shared__ __align__(8) uint64_t s_empty[NSTAGE];
    uint32_t sbase = (smem_u32(dsm) + 1023) & ~1023u;   // 1024B-align: swizzle phase contract
    int tid = threadIdx.x;
    int lane = tid & 31;
    int wid = tid >> 5;
    int wr = wid & 1;      // warp row: m offset wr*64
    int wc = wid >> 1;     // warp col: n offset wc*32
    int bm = blockIdx.y * 128;
    int bn = blockIdx.x * 128;

    float acc[4][4][4];
    #pragma unroll
    for (int mi = 0; mi < 4; mi++)
        #pragma unroll
        for (int ni = 0; ni < 4; ni++)
            #pragma unroll
            for (int q = 0; q < 4; q++) acc[mi][ni][q] = 0.f;

    const int NC = Kk >> 6;   // BKT=64 chunks

    if (tid == 0) {
        #pragma unroll
        for (int s = 0; s < NSTAGE; s++) {
            MBAR_INIT(smem_u32(&s_full[s]), 1);
            MBAR_INIT(smem_u32(&s_empty[s]), 8);   // one arrive per warp (lane0)
        }
    }
    __syncthreads();

    // prologue: issue chunks 0, 1
    if (tid == 0) {
        FENCE_ASYNC();   // order barrier inits (generic) before async-proxy use
        #pragma unroll
        for (int c0 = 0; c0 < 2; c0++) {
            if (c0 < NC) {
                uint32_t st = sbase + c0 * STAGE_BYTES;
                uint32_t mb = smem_u32(&s_full[c0]);
                MBAR_EXPECT(mb, STAGE_BYTES);
                TMA_LD2D(st + OFF_A, &tmA, c0 << 6, bm, mb);
                TMA_LD2D(st + OFF_B, &tmB, c0 << 6, bn, mb);
            }
        }
    }

    int a_row = wr * 64 + (lane & 15);
    int a_usel = (lane >> 4) & 1;
    int b_row = wc * 32 + (lane & 7) + ((lane >> 4) & 1) * 8;
    int b_usel = (lane >> 3) & 1;

    for (int c = 0; c < NC; c++) {
        int stg = c % NSTAGE;
        MBAR_WAIT(smem_u32(&s_full[stg]), (c / NSTAGE) & 1);

        uint32_t st = sbase + stg * STAGE_BYTES;
        #pragma unroll
        for (int kk = 0; kk < 4; kk++) {
            uint32_t bh[8];
            #pragma unroll
            for (int g = 0; g < 2; g++) {
                int r = b_row + g * 16;
                uint32_t off = sw_off(r, kk * 2 + b_usel);
                LDMX4(bh[g*4+0], bh[g*4+1], bh[g*4+2], bh[g*4+3], st + OFF_B + off);
            }
            #pragma unroll
            for (int mi = 0; mi < 4; mi++) {
                uint32_t ah[4];
                int r = a_row + mi * 16;
                uint32_t off = sw_off(r, kk * 2 + a_usel);
                LDMX4(ah[0], ah[1], ah[2], ah[3], st + OFF_A + off);
                #pragma unroll
                for (int ni = 0; ni < 4; ni++) {
                    MMA_F16(acc[mi][ni], ah, bh[ni*2], bh[ni*2+1]);
                }
            }
        }
        // warp done with this stage's smem; ldmatrix is warp-collective, so lane0's
        // program order covers all lanes' reads (release pairs with producer acquire)
        if (lane == 0) MBAR_ARRIVE(smem_u32(&s_empty[stg]));

        if (tid == 0 && c + 2 < NC) {
            int cn = c + 2;
            int sn = cn % NSTAGE;
            if (cn >= NSTAGE)
                MBAR_WAIT(smem_u32(&s_empty[sn]), (cn / NSTAGE - 1) & 1);
            // order all consumers' generic-proxy reads before the async-proxy TMA write
            FENCE_ASYNC();
            uint32_t st2 = sbase + sn * STAGE_BYTES;
            uint32_t mb = smem_u32(&s_full[sn]);
            MBAR_EXPECT(mb, STAGE_BYTES);
            TMA_LD2D(st2 + OFF_A, &tmA, cn << 6, bm, mb);
            TMA_LD2D(st2 + OFF_B, &tmB, cn << 6, bn, mb);
        }
    }

    // epilogue
    int m0 = bm + wr * 64 + (lane >> 2);
    int n0 = bn + wc * 32 + (lane & 3) * 2;
    #pragma unroll
    for (int mi = 0; mi < 4; mi++) {
        #pragma unroll
        for (int r2 = 0; r2 < 2; r2++) {
            int row = m0 + mi * 16 + r2 * 8;
            size_t rbase = (size_t)row * Nn;
            #pragma unroll
            for (int ni = 0; ni < 4; ni++) {
                int col = n0 + ni * 8;
                float v0 = acc[mi][ni][r2*2+0] + bias[col];
                float v1 = acc[mi][ni][r2*2+1] + bias[col+1];
                if (epi == 0) {
                    *(__half2*)(outH + rbase + col) = __floats2half2_rn(v0, v1);
                } else if (epi == 2) {
                    v0 = gelu_tanh(v0); v1 = gelu_tanh(v1);
                    *(__half2*)(outH + rbase + col) = __floats2half2_rn(v0, v1);
                } else if (epi == 3) {
                    float2 rv = *(const float2*)(resF + rbase + col);
                    *(__half2*)(outH + rbase + col) = __floats2half2_rn(v0 + rv.x, v1 + rv.y);
                } else {
                    float2 rv = __half22float2(*(const __half2*)(resH + rbase + col));
                    *(float2*)(outF + rbase + col) = make_float2(v0 + rv.x, v1 + rv.y);
                }
            }
        }
    }
}

// ---------------- Sliding-window causal attention (W=16), fp16, dual-query warps ----------------
// Lanes 0-15 score query A, lanes 16-31 score query B. Q, K, V staged in smem.
#define TQ 64
#define KR (TQ + WW - 1)     // 79 key rows
#define PKH 72               // halves per smem row (144B, 16B-aligned rows)
#define ATTN_SMEM ((2 * 80 + 64) * PKH * 2)   // K + V + Q = 32256 bytes

__global__ __launch_bounds__(256, 6)
void attn_kernel(const __half* __restrict__ qkv,
                 __half* __restrict__ oh) {
    extern __shared__ __align__(16) __half asm_h[];
    __half* Ks = asm_h;                 // [80][PKH]
    __half* Vs = asm_h + 80 * PKH;      // [80][PKH]
    __half* Qs = asm_h + 160 * PKH;     // [64][PKH]

    int tile = blockIdx.x;
    int h = blockIdx.y;
    int b = blockIdx.z;
    int s0 = tile * TQ;
    int tid = threadIdx.x;
    int lane = tid & 31;
    int w = tid >> 5;

    // cooperative K/V load: 79 rows x 64 halves, 16B chunks; zero-fill seq<0 rows
    for (int i = tid; i < KR * (HD / 8); i += 256) {
        int r = i >> 3;
        int c = (i & 7) * 8;
        int seq = s0 - (WW - 1) + r;
        if (seq >= 0) {
            size_t base = ((size_t)(b * SS + seq)) * (3 * DD) + h * HD + c;
            *(float4*)&Ks[r * PKH + c] = *(const float4*)(qkv + base + DD);
            *(float4*)&Vs[r * PKH + c] = *(const float4*)(qkv + base + 2 * DD);
        } else {
            float4 z = make_float4(0.f, 0.f, 0.f, 0.f);
            *(float4*)&Ks[r * PKH + c] = z;
            *(float4*)&Vs[r * PKH + c] = z;
        }
    }
    // cooperative Q load: 64 rows x 64 halves
    for (int i = tid; i < TQ * (HD / 8); i += 256) {
        int r = i >> 3;
        int c = (i & 7) * 8;
        size_t base = ((size_t)(b * SS + s0 + r)) * (3 * DD) + h * HD + c;
        *(float4*)&Qs[r * PKH + c] = *(const float4*)(qkv + base);
    }
    __syncthreads();

    int half = lane >> 4;   // 0: query A, 1: query B
    int hl = lane & 15;     // key offset j for the score phase

    for (int qq = 0; qq < 4; qq++) {
        int qi = w * 8 + qq * 2 + half;   // this lane's score query (local)
        int s = s0 + qi;

        float score = -INFINITY;
        if (hl <= s) {
            const __half* qp = &Qs[qi * PKH];
            const __half* kp = &Ks[(qi + WW - 1 - hl) * PKH];
            float acc = 0.f;
            #pragma unroll
            for (int d = 0; d < HD; d += 8) {
                float4 qa4 = *(const float4*)(qp + d);
                float4 ka4 = *(const float4*)(kp + d);
                const __half2* qh = (const __half2*)&qa4;
                const __half2* kh = (const __half2*)&ka4;
                #pragma unroll
                for (int t = 0; t < 4; t++) {
                    float2 qf = __half22float2(qh[t]);
                    float2 kf = __half22float2(kh[t]);
                    acc = fmaf(qf.x, kf.x, acc);
                    acc = fmaf(qf.y, kf.y, acc);
                }
            }
            score = acc * 0.125f;
        }
        // 16-lane reductions (XOR < 16 stays within each half-warp)
        float mx = score;
        #pragma unroll
        for (int o = 8; o > 0; o >>= 1) mx = fmaxf(mx, __shfl_xor_sync(0xffffffffu, mx, o));
        float p = (score == -INFINITY) ? 0.f : __expf(score - mx);
        float sum = p;
        #pragma unroll
        for (int o = 8; o > 0; o >>= 1) sum += __shfl_xor_sync(0xffffffffu, sum, o);
        float inv = 1.f / sum;
        float invA = __shfl_sync(0xffffffffu, inv, 0);
        float invB = __shfl_sync(0xffffffffu, inv, 16);

        // V accumulation for both queries; lane owns dims 2*lane, 2*lane+1
        int qiA = w * 8 + qq * 2;
        int qiB = qiA + 1;
        float a0 = 0.f, a1 = 0.f, b0 = 0.f, b1 = 0.f;
        #pragma unroll
        for (int jj = 0; jj < WW; jj++) {
            float pA = __shfl_sync(0xffffffffu, p, jj);
            float pB = __shfl_sync(0xffffffffu, p, 16 + jj);
            float2 vA = __half22float2(*(const __half2*)&Vs[(qiA + WW - 1 - jj) * PKH + 2 * lane]);
            float2 vB = __half22float2(*(const __half2*)&Vs[(qiB + WW - 1 - jj) * PKH + 2 * lane]);
            a0 = fmaf(pA, vA.x, a0); a1 = fmaf(pA, vA.y, a1);
            b0 = fmaf(pB, vB.x, b0); b1 = fmaf(pB, vB.y, b1);
        }
        size_t mA = (size_t)(b * SS + s0 + qiA);
        *(__half2*)(oh + mA * DD + h * HD + 2 * lane)       = __floats2half2_rn(a0 * invA, a1 * invA);
        *(__half2*)(oh + (mA + 1) * DD + h * HD + 2 * lane) = __floats2half2_rn(b0 * invB, b1 * invB);
    }
}

// ---------------- launch ----------------
typedef CUresult (*PFN_encode)(CUtensorMap*, CUtensorMapDataType, cuuint32_t, void*,
                               const cuuint64_t*, const cuuint64_t*, const cuuint32_t*,
                               const cuuint32_t*, CUtensorMapInterleave, CUtensorMapSwizzle,
                               CUtensorMapL2promotion, CUtensorMapFloatOOBfill);

static void make_map(PFN_encode enc, CUtensorMap* m, void* ptr, uint64_t K, uint64_t R) {
    cuuint64_t dims[2]    = {K, R};
    cuuint64_t strides[1] = {K * 2};
    cuuint32_t box[2]     = {64, 128};
    cuuint32_t es[2]      = {1, 1};
    enc(m, CU_TENSOR_MAP_DATA_TYPE_FLOAT16, 2, ptr, dims, strides, box, es,
        CU_TENSOR_MAP_INTERLEAVE_NONE, CU_TENSOR_MAP_SWIZZLE_128B,
        CU_TENSOR_MAP_L2_PROMOTION_L2_128B, CU_TENSOR_MAP_FLOAT_OOB_FILL_NONE);
}

extern "C" void kernel_launch(void* const* d_in, const int* in_sizes, int n_in,
                              void* d_out, int out_size) {
    const float* x          = (const float*)d_in[0];
    const float* ln1_g      = (const float*)d_in[1];
    const float* ln1_b      = (const float*)d_in[2];
    const float* in_proj_w  = (const float*)d_in[3];
    const float* in_proj_b  = (const float*)d_in[4];
    const float* out_proj_w = (const float*)d_in[5];
    const float* out_proj_b = (const float*)d_in[6];
    const float* ln2_g      = (const float*)d_in[7];
    const float* ln2_b      = (const float*)d_in[8];
    const float* mlp_w1     = (const float*)d_in[9];
    const float* mlp_b1     = (const float*)d_in[10];
    const float* mlp_w2     = (const float*)d_in[11];
    const float* mlp_b2     = (const float*)d_in[12];
    float* out = (float*)d_out;

    __half *p_qkvh, *p_x1h, *p_h, *p_at, *p_xn, *p_ff, *p_wq, *p_wo, *p_w1, *p_w2;
    cudaGetSymbolAddress((void**)&p_qkvh, g_qkv_h);
    cudaGetSymbolAddress((void**)&p_x1h, g_x1_h);
    cudaGetSymbolAddress((void**)&p_h,   g_h_h);
    cudaGetSymbolAddress((void**)&p_at,  g_at_h);
    cudaGetSymbolAddress((void**)&p_xn,  g_xn_h);
    cudaGetSymbolAddress((void**)&p_ff,  g_ff_h);
    cudaGetSymbolAddress((void**)&p_wq,  g_wq_h);
    cudaGetSymbolAddress((void**)&p_wo,  g_wo_h);
    cudaGetSymbolAddress((void**)&p_w1,  g_w1_h);
    cudaGetSymbolAddress((void**)&p_w2,  g_w2_h);

    // driver entry point via runtime API (no -lcuda needed)
    PFN_encode enc = nullptr;
    cudaDriverEntryPointQueryResult qr;
    cudaGetDriverEntryPoint("cuTensorMapEncodeTiled", (void**)&enc,
                            cudaEnableDefault, &qr);

    CUtensorMap tm_h, tm_wq, tm_at, tm_wo, tm_xn, tm_w1, tm_ff, tm_w2;
    make_map(enc, &tm_h,  p_h,  DD,  MM);
    make_map(enc, &tm_wq, p_wq, DD,  3 * DD);
    make_map(enc, &tm_at, p_at, DD,  MM);
    make_map(enc, &tm_wo, p_wo, DD,  DD);
    make_map(enc, &tm_xn, p_xn, DD,  MM);
    make_map(enc, &tm_w1, p_w1, DD,  DFF);
    make_map(enc, &tm_ff, p_ff, DFF, MM);
    make_map(enc, &tm_w2, p_w2, DFF, DD);

    cudaFuncSetAttribute(gemmh, cudaFuncAttributeMaxDynamicSharedMemorySize, GEMM_SMEM);
    cudaFuncSetAttribute(attn_kernel, cudaFuncAttributeMaxDynamicSharedMemorySize, ATTN_SMEM);

    cvt4_kernel<<<12288, 256>>>(in_proj_w, p_wq, out_proj_w, p_wo,
                                mlp_w1, p_w1, mlp_w2, p_w2);
    ln_half_kernel<<<MM, 256>>>(x, ln1_g, ln1_b, p_h);
    // QKV = h @ W_in^T + b -> fp16   [4096, 3072]
    gemmh<<<dim3(3 * DD / 128, MM / 128), 256, GEMM_SMEM>>>(
        tm_h, tm_wq, in_proj_b, nullptr, nullptr, nullptr, p_qkvh, 3 * DD, DD, 0);
    // windowed attention (fp16 smem-tiled, dual-query, Q/K/V smem) -> fp16
    attn_kernel<<<dim3(SS / TQ, HH, BB), 256, ATTN_SMEM>>>(p_qkvh, p_at);
    // out proj + residual(x) -> x1 fp16  [4096, 1024]
    gemmh<<<dim3(DD / 128, MM / 128), 256, GEMM_SMEM>>>(
        tm_at, tm_wo, out_proj_b, x, nullptr, nullptr, p_x1h, DD, DD, 3);
    // LN2 (fp16 in) -> fp16
    ln_half_in_kernel<<<MM, 256>>>(p_x1h, ln2_g, ln2_b, p_xn);
    // MLP up + GELU -> fp16   [4096, 4096]
    gemmh<<<dim3(DFF / 128, MM / 128), 256, GEMM_SMEM>>>(
        tm_xn, tm_w1, mlp_b1, nullptr, nullptr, nullptr, p_ff, DFF, DD, 2);
    // MLP down + residual(x1 fp16) -> out fp32   [4096, 1024]
    gemmh<<<dim3(DD / 128, MM / 128), 256, GEMM_SMEM>>>(
        tm_ff, tm_w2, mlp_b2, nullptr, p_x1h, out, nullptr, DD, DFF, 4);
}